// round 17
// baseline (speedup 1.0000x reference)
#include <cuda_runtime.h>
#include <cuda_fp16.h>
#include <cstdint>
#include <math.h>

// Problem constants: B=4, S=2048, D=2048, H=16, hd=128
#define Bb_ 4
#define S_  2048
#define H_  16
#define HD_ 128
#define D_  2048

// ---------------- scratch (device globals; allocation-free) ----------------
__device__ __half g_qh[16777216];     // post-rope Q fp16 [B,H,S,hd]
__device__ __half g_kh[16777216];     // post-rope K fp16
__device__ __half g_vh[16777216];     // V fp16
__device__ __half g_xh[16777216];     // x fp16 [8192,2048]
__device__ __half g_wqh[12582912];    // w_qkv^T fp16 [6144,2048]
__device__ __half g_woh[4194304];     // w_out^T fp16 [2048,2048]
__device__ __half g_ah[16777216];     // attn fp16 [B,S,D]

// ---------------- helpers ----------------
__device__ __forceinline__ uint32_t smem_u32(const void* p) {
    uint32_t a;
    asm("{ .reg .u64 t; cvta.to.shared.u64 t, %1; cvt.u32.u64 %0, t; }" : "=r"(a) : "l"(p));
    return a;
}
__device__ __forceinline__ void ldsm4(uint32_t* r, uint32_t addr) {
    asm volatile("ldmatrix.sync.aligned.m8n8.x4.shared.b16 {%0,%1,%2,%3}, [%4];"
                 : "=r"(r[0]), "=r"(r[1]), "=r"(r[2]), "=r"(r[3]) : "r"(addr));
}
__device__ __forceinline__ void ldsm4t(uint32_t* r, uint32_t addr) {
    asm volatile("ldmatrix.sync.aligned.m8n8.x4.trans.shared.b16 {%0,%1,%2,%3}, [%4];"
                 : "=r"(r[0]), "=r"(r[1]), "=r"(r[2]), "=r"(r[3]) : "r"(addr));
}
__device__ __forceinline__ void mma_f16(float* c, const uint32_t* a, uint32_t b0, uint32_t b1) {
    asm volatile(
        "mma.sync.aligned.m16n8k16.row.col.f32.f16.f16.f32 "
        "{%0,%1,%2,%3}, {%4,%5,%6,%7}, {%8,%9}, {%0,%1,%2,%3};"
        : "+f"(c[0]), "+f"(c[1]), "+f"(c[2]), "+f"(c[3])
        : "r"(a[0]), "r"(a[1]), "r"(a[2]), "r"(a[3]), "r"(b0), "r"(b1));
}
__device__ __forceinline__ uint32_t sw128(uint32_t off) { return off ^ ((off >> 3) & 0x70); }
__device__ __forceinline__ void cpa16(uint32_t dst, const void* src) {
    asm volatile("cp.async.cg.shared.global [%0], [%1], 16;" :: "r"(dst), "l"(src));
}
__device__ __forceinline__ void cpa_commit() { asm volatile("cp.async.commit_group;" ::: "memory"); }
__device__ __forceinline__ void cpa_wait0()  { asm volatile("cp.async.wait_group 0;" ::: "memory"); }
__device__ __forceinline__ void cpa_wait1()  { asm volatile("cp.async.wait_group 1;" ::: "memory"); }
__device__ __forceinline__ float ex2(float x) {
    float r; asm("ex2.approx.f32 %0, %1;" : "=f"(r) : "f"(x)); return r;
}
__device__ __forceinline__ uint32_t packh(float a, float b) {
    __half ha = __float2half(a), hb = __float2half(b);
    return (uint32_t)__half_as_ushort(ha) | ((uint32_t)__half_as_ushort(hb) << 16);
}

// ---------------- one-time conversion kernels ----------------
__global__ void round_f32h(const float* __restrict__ src, __half* __restrict__ dst)
{
    const long long i = (long long)blockIdx.x * 256 + threadIdx.x;   // per float4
    float4 v = ((const float4*)src)[i];
    uint2 h;
    h.x = packh(v.x, v.y);
    h.y = packh(v.z, v.w);
    ((uint2*)dst)[i] = h;
}

// transpose + fp16 round: dst[C][R] = fp16(src[R][C])
__global__ void transpose_h(const float* __restrict__ src, __half* __restrict__ dst,
                            int R, int Cc)
{
    __shared__ float t[32][33];
    const int bx = blockIdx.x * 32, by = blockIdx.y * 32;
    const int txx = threadIdx.x, tyy = threadIdx.y;
#pragma unroll
    for (int i = 0; i < 4; ++i)
        t[tyy + i * 8][txx] = src[(long long)(by + tyy + i * 8) * Cc + bx + txx];
    __syncthreads();
#pragma unroll
    for (int i = 0; i < 4; ++i)
        dst[(long long)(bx + tyy + i * 8) * R + by + txx] = __float2half(t[txx][tyy + i * 8]);
}

// ---------------- fp16 mma.sync TN GEMM, 128x128 tile, 2 CTAs/SM ----------
// C[M,N] = Ah[M,K] @ Bh[N,K]^T, fp32 accum. Block 128x128, 8 warps (4x2),
// warp tile 32x64, K chunk 64, 3-stage cp.async, __launch_bounds__(256,2).
// MODE: 0 = plain fp32 C write,
//       1 = qkv: q,k get fused RoPE (smem tile exchange) -> fp16; v -> fp16
#define SMEM_GEMM_BYTES 99328   // 1024 + 3 * 32768 (also >= 128*132*4 staging)
#define TOFF(buf, which) (1024u + (uint32_t)(buf) * 32768u + (uint32_t)(which) * 16384u)

// one 128x64 fp16 tile -> SW128 smem via cp.async (256 threads, 4 per thread)
__device__ __forceinline__ void cpa_tile(uint32_t sdst, const __half* __restrict__ src,
                                         int ld, int row0, int kbase, int tid) {
#pragma unroll
    for (int p = 0; p < 4; ++p) {
        const int g = tid + p * 256;         // 0..1023
        const int row = g >> 3;              // 0..127
        const int seg = g & 7;               // 16B segment
        cpa16(sdst + sw128(row * 128 + seg * 16),
              src + (long long)(row0 + row) * ld + kbase + seg * 8);
    }
}

template<int MODE>
__global__ __launch_bounds__(256, 2)
void gemm_hf(const __half* __restrict__ Ah, const __half* __restrict__ Bh,
             float* __restrict__ C, int K, int lda, int ldb, int ldc,
             const float* __restrict__ cosT, const float* __restrict__ sinT)
{
    const int m0 = blockIdx.y * 128;
    const int n0 = blockIdx.x * 128;
    const int nchunks = K >> 6;

    extern __shared__ char smem[];
    const uint32_t sb = smem_u32(smem);
    const int tid = threadIdx.x;
    const int lane = tid & 31;
    const int wid = tid >> 5;
    const int wm = (wid & 3) * 32;
    const int wn = (wid >> 2) * 64;
    const int lq = lane >> 3, lr = lane & 7;

    const int a_row = wm + (lq & 1) * 8 + lr;
    const int a_kc2 = (lq >> 1) * 16;
    const int b_row = wn + (lq >> 1) * 8 + lr;
    const int b_kc2 = (lq & 1) * 16;

    float acc[2][8][4];
#pragma unroll
    for (int i = 0; i < 2; i++)
#pragma unroll
        for (int j = 0; j < 8; j++)
#pragma unroll
            for (int e = 0; e < 4; e++) acc[i][j][e] = 0.f;

    // prologue: stage chunks 0 and 1 as separate commit groups
    cpa_tile(sb + TOFF(0, 0), Ah, lda, m0, 0, tid);
    cpa_tile(sb + TOFF(0, 1), Bh, ldb, n0, 0, tid);
    cpa_commit();
    cpa_tile(sb + TOFF(1, 0), Ah, lda, m0, 64, tid);
    cpa_tile(sb + TOFF(1, 1), Bh, ldb, n0, 64, tid);
    cpa_commit();
    cpa_wait1();            // chunk 0 resident
    __syncthreads();

    for (int c = 0; c < nchunks; ++c) {
        const int buf = c % 3;
        if (c + 2 < nchunks) {
            const int nb = (c + 2) % 3;
            const int kb = (c + 2) * 64;
            cpa_tile(sb + TOFF(nb, 0), Ah, lda, m0, kb, tid);
            cpa_tile(sb + TOFF(nb, 1), Bh, ldb, n0, kb, tid);
        }
        cpa_commit();

        const uint32_t sA = sb + TOFF(buf, 0);
        const uint32_t sB = sb + TOFF(buf, 1);
#pragma unroll
        for (int kk = 0; kk < 4; ++kk) {
            uint32_t aF[2][4], bF[4][4];
#pragma unroll
            for (int i = 0; i < 2; ++i)
                ldsm4(aF[i], sA + sw128((a_row + i * 16) * 128 + kk * 32 + a_kc2));
#pragma unroll
            for (int jp = 0; jp < 4; ++jp)
                ldsm4(bF[jp], sB + sw128((b_row + jp * 16) * 128 + kk * 32 + b_kc2));
#pragma unroll
            for (int i = 0; i < 2; ++i)
#pragma unroll
                for (int jp = 0; jp < 4; ++jp) {
                    mma_f16(acc[i][2 * jp],     aF[i], bF[jp][0], bF[jp][1]);
                    mma_f16(acc[i][2 * jp + 1], aF[i], bF[jp][2], bF[jp][3]);
                }
        }

        cpa_wait1();
        __syncthreads();
    }

    const int lm = lane >> 2;
    const int ln = (lane & 3) * 2;

    if (MODE == 0) {
#pragma unroll
        for (int i = 0; i < 2; ++i)
#pragma unroll
            for (int j = 0; j < 8; ++j) {
                const int gn = n0 + wn + j * 8 + ln;
#pragma unroll
                for (int half = 0; half < 2; ++half) {
                    const int gm = m0 + wm + i * 16 + lm + half * 8;
                    *(float2*)(C + (long long)gm * ldc + gn) =
                        make_float2(acc[i][j][half * 2], acc[i][j][half * 2 + 1]);
                }
            }
    } else {
        // Each CTA covers one head slab: t,h constant; d spans 0..127.
        const int t = n0 >> 11, h = (n0 >> 7) & 15;
        if (t < 2) {
            // stage fp32 tile for cross-warp rope-pair exchange
            float* st = (float*)smem;   // 128 x 132 floats = 67584 B
#pragma unroll
            for (int i = 0; i < 2; ++i)
#pragma unroll
                for (int j = 0; j < 8; ++j)
#pragma unroll
                    for (int half = 0; half < 2; ++half) {
                        const int r = wm + i * 16 + lm + half * 8;
                        const int cc = wn + j * 8 + ln;
                        *(float2*)(st + r * 132 + cc) =
                            make_float2(acc[i][j][half * 2], acc[i][j][half * 2 + 1]);
                    }
            __syncthreads();
            __half* dstbuf = (t == 0) ? g_qh : g_kh;
#pragma unroll
            for (int i = 0; i < 2; ++i)
#pragma unroll
                for (int j = 0; j < 8; ++j)
#pragma unroll
                    for (int half = 0; half < 2; ++half) {
                        const int r = wm + i * 16 + lm + half * 8;
                        const int d = wn + j * 8 + ln;
                        const int gm = m0 + r;
                        const int b = gm >> 11, s_ = gm & 2047;
                        const int i0 = d & 63;
                        const float c0 = cosT[s_ * 64 + i0],     sv0 = sinT[s_ * 64 + i0];
                        const float c1 = cosT[s_ * 64 + i0 + 1], sv1 = sinT[s_ * 64 + i0 + 1];
                        const float v0 = st[r * 132 + d],       v1 = st[r * 132 + d + 1];
                        const float p0 = st[r * 132 + (d ^ 64)], p1 = st[r * 132 + ((d + 1) ^ 64)];
                        float o0, o1;
                        if (d < 64) { o0 = v0 * c0 - p0 * sv0; o1 = v1 * c1 - p1 * sv1; }
                        else        { o0 = p0 * sv0 + v0 * c0; o1 = p1 * sv1 + v1 * c1; }
                        const long long idx = ((long long)(b * H_ + h) * S_ + s_) * HD_ + d;
                        *(uint32_t*)(dstbuf + idx) = packh(o0, o1);
                    }
        } else {
            // V: direct fp16 store
#pragma unroll
            for (int i = 0; i < 2; ++i)
#pragma unroll
                for (int j = 0; j < 8; ++j) {
                    const int d = wn + j * 8 + ln;
#pragma unroll
                    for (int half = 0; half < 2; ++half) {
                        const int gm = m0 + wm + i * 16 + lm + half * 8;
                        const int b = gm >> 11, s_ = gm & 2047;
                        const long long idx = ((long long)(b * H_ + h) * S_ + s_) * HD_ + d;
                        *(uint32_t*)(g_vh + idx) =
                            packh(acc[i][j][half * 2], acc[i][j][half * 2 + 1]);
                    }
                }
        }
    }
}

// ---------------- fused flash attention (fp16, fp32 accum, 2 CTAs/SM) ------
// CTA: (q-tile 128, bh). 8 warps x 16 q-rows. K/V chunks 64 rows, double-
// buffered cp.async. Scores in registers; MMA1 C-frag repacked as MMA2 A-frag.
// smem: Q 32KB @0; kv buf b @32768+b*32768: Kh 16KB, Vh 16KB.
#define FA_SMEM 98304

__device__ __forceinline__ void fa_load_kv(uint32_t kvbase, int bh, int s0, int tid) {
#pragma unroll
    for (int p = 0; p < 4; ++p) {
        const int g = tid + p * 256;          // 0..1023
        const int row = g >> 4;               // 0..63
        const int b16i = g & 15;
        const uint32_t byte = b16i * 16;
        const long long srcoff = (((long long)(bh << 11) + s0 + row) << 7) + b16i * 8;
        const uint32_t dst = kvbase + (byte >> 7) * 8192 + sw128(row * 128 + (byte & 127));
        cpa16(dst,         g_kh + srcoff);
        cpa16(dst + 16384, g_vh + srcoff);
    }
}

__global__ __launch_bounds__(256, 2)
void flash_attn()
{
    const int qt = 15 - blockIdx.x;           // big tiles first
    const int q0 = qt << 7;
    const int bh = blockIdx.y;
    const int nch = (qt + 1) * 2;

    extern __shared__ char smem[];
    const uint32_t sb = smem_u32(smem);
    const int tid = threadIdx.x;
    const int w = tid >> 5;
    const int lane = tid & 31;
    const int wq = w * 16;
    const int lq = lane >> 3, lr = lane & 7;
    const int lc = lane & 3;
    const int lrow = lane >> 2;

    // prologue: Q + chunk 0
#pragma unroll
    for (int p = 0; p < 4; ++p) {
        const int g = tid + p * 256;          // 0..1023
        const int row = g >> 3;               // 0..127
        const int b16i = g & 7;
        const uint32_t byte0 = b16i * 16;
        const long long srcoff0 = (((long long)(bh << 11) + q0 + row) << 7) + b16i * 8;
        cpa16(sb + (byte0 >> 7) * 16384 + sw128(row * 128 + (byte0 & 127)), g_qh + srcoff0);
        const uint32_t byte1 = byte0 + 128;
        const long long srcoff1 = srcoff0 + 64;
        cpa16(sb + (byte1 >> 7) * 16384 + sw128(row * 128 + (byte1 & 127)), g_qh + srcoff1);
    }
    fa_load_kv(sb + 32768, bh, 0, tid);
    cpa_commit();
    cpa_wait0();
    __syncthreads();

    const float C = 0.08838834764831845f * 1.4426950408889634f; // scale*log2(e)
    float o[16][4];
#pragma unroll
    for (int t = 0; t < 16; ++t)
#pragma unroll
        for (int e = 0; e < 4; ++e) o[t][e] = 0.f;
    float m0 = -1e30f, m1 = -1e30f, l0 = 0.f, l1 = 0.f;

    for (int c = 0; c < nch; ++c) {
        const uint32_t kvb = sb + 32768 + (uint32_t)(c & 1) * 32768;
        if (c + 1 < nch) {
            fa_load_kv(sb + 32768 + (uint32_t)((c + 1) & 1) * 32768, bh, (c + 1) * 64, tid);
            cpa_commit();
        }

        // MMA1: scores[16q x 64k] = Q @ K^T
        float s[8][4];
#pragma unroll
        for (int j = 0; j < 8; ++j)
#pragma unroll
            for (int e = 0; e < 4; ++e) s[j][e] = 0.f;

#pragma unroll
        for (int kk = 0; kk < 8; ++kk) {
            const int arow = wq + (lq & 1) * 8 + lr;
            const uint32_t akb = kk * 32 + (lq >> 1) * 16;
            const uint32_t qaddr = sb + (akb >> 7) * 16384 + sw128(arow * 128 + (akb & 127));
            uint32_t a4[4];
            ldsm4(a4, qaddr);
#pragma unroll
            for (int nt = 0; nt < 4; ++nt) {
                const int brow = nt * 16 + (lq >> 1) * 8 + lr;
                const uint32_t bkb = kk * 32 + (lq & 1) * 16;
                const uint32_t kaddr = kvb + (bkb >> 7) * 8192 + sw128(brow * 128 + (bkb & 127));
                uint32_t b4[4];
                ldsm4(b4, kaddr);
                mma_f16(s[2 * nt],     a4, b4[0], b4[1]);
                mma_f16(s[2 * nt + 1], a4, b4[2], b4[3]);
            }
        }

        // causal mask near diagonal
        if (c * 64 + 63 > q0 + wq) {
            const int r0g = q0 + wq + lrow;
#pragma unroll
            for (int j = 0; j < 8; ++j) {
                const int k0 = c * 64 + 8 * j + 2 * lc;
                if (k0 > r0g)         s[j][0] = -1e30f;
                if (k0 + 1 > r0g)     s[j][1] = -1e30f;
                if (k0 > r0g + 8)     s[j][2] = -1e30f;
                if (k0 + 1 > r0g + 8) s[j][3] = -1e30f;
            }
        }

        // online softmax
        float mx0 = -1e30f, mx1 = -1e30f;
#pragma unroll
        for (int j = 0; j < 8; ++j) {
            mx0 = fmaxf(mx0, fmaxf(s[j][0], s[j][1]));
            mx1 = fmaxf(mx1, fmaxf(s[j][2], s[j][3]));
        }
        mx0 = fmaxf(mx0, __shfl_xor_sync(0xffffffffu, mx0, 1));
        mx0 = fmaxf(mx0, __shfl_xor_sync(0xffffffffu, mx0, 2));
        mx1 = fmaxf(mx1, __shfl_xor_sync(0xffffffffu, mx1, 1));
        mx1 = fmaxf(mx1, __shfl_xor_sync(0xffffffffu, mx1, 2));
        const float mn0 = fmaxf(m0, mx0), mn1 = fmaxf(m1, mx1);
        const float al0 = ex2((m0 - mn0) * C), al1 = ex2((m1 - mn1) * C);
        m0 = mn0; m1 = mn1;
        l0 *= al0; l1 *= al1;
#pragma unroll
        for (int t = 0; t < 16; ++t) {
            o[t][0] *= al0; o[t][1] *= al0; o[t][2] *= al1; o[t][3] *= al1;
        }
        uint32_t ph[8][2];
#pragma unroll
        for (int j = 0; j < 8; ++j) {
            float p0 = ex2((s[j][0] - m0) * C);
            float p1 = ex2((s[j][1] - m0) * C);
            float p2 = ex2((s[j][2] - m1) * C);
            float p3 = ex2((s[j][3] - m1) * C);
            l0 += p0 + p1; l1 += p2 + p3;
            ph[j][0] = packh(p0, p1);
            ph[j][1] = packh(p2, p3);
        }

        // MMA2: O += P @ V (V via trans ldmatrix)
#pragma unroll
        for (int kk = 0; kk < 4; ++kk) {
            uint32_t pa[4] = { ph[2 * kk][0], ph[2 * kk][1], ph[2 * kk + 1][0], ph[2 * kk + 1][1] };
#pragma unroll
            for (int nt = 0; nt < 8; ++nt) {
                const int vrow = kk * 16 + (lq & 1) * 8 + lr;
                const uint32_t nb = nt * 32 + (lq >> 1) * 16;
                const uint32_t vaddr = kvb + 16384 + (nb >> 7) * 8192 + sw128(vrow * 128 + (nb & 127));
                uint32_t v4[4];
                ldsm4t(v4, vaddr);
                mma_f16(o[2 * nt],     pa, v4[0], v4[1]);
                mma_f16(o[2 * nt + 1], pa, v4[2], v4[3]);
            }
        }

        cpa_wait0();
        __syncthreads();
    }

    l0 += __shfl_xor_sync(0xffffffffu, l0, 1);
    l0 += __shfl_xor_sync(0xffffffffu, l0, 2);
    l1 += __shfl_xor_sync(0xffffffffu, l1, 1);
    l1 += __shfl_xor_sync(0xffffffffu, l1, 2);
    const float inv0 = 1.f / l0, inv1 = 1.f / l1;

    // write attn as fp16 [B,S,D]
    const int b = bh >> 4, h = bh & 15;
    const int row0 = q0 + wq + lrow;
    const long long base0 = ((long long)(b * S_ + row0)) * D_ + h * HD_ + 2 * lc;
    const long long base1 = base0 + 8LL * D_;
#pragma unroll
    for (int t = 0; t < 16; ++t) {
        *(uint32_t*)(g_ah + base0 + 8 * t) = packh(o[t][0] * inv0, o[t][1] * inv0);
        *(uint32_t*)(g_ah + base1 + 8 * t) = packh(o[t][2] * inv1, o[t][3] * inv1);
    }
}

// ---------------- launch ----------------
extern "C" void kernel_launch(void* const* d_in, const int* in_sizes, int n_in,
                              void* d_out, int out_size)
{
    const float* x     = (const float*)d_in[0]; // [4,2048,2048]
    const float* cosT  = (const float*)d_in[1]; // [2048,64]
    const float* sinT  = (const float*)d_in[2]; // [2048,64]
    const float* w_qkv = (const float*)d_in[3]; // [2048,6144]
    const float* w_out = (const float*)d_in[4]; // [2048,2048]
    float* out = (float*)d_out;                 // [4,2048,2048]
    (void)in_sizes; (void)n_in; (void)out_size;

    __half *xh, *wqh, *woh, *ah;
    cudaGetSymbolAddress((void**)&xh, g_xh);
    cudaGetSymbolAddress((void**)&wqh, g_wqh);
    cudaGetSymbolAddress((void**)&woh, g_woh);
    cudaGetSymbolAddress((void**)&ah, g_ah);

    cudaFuncSetAttribute(gemm_hf<0>, cudaFuncAttributeMaxDynamicSharedMemorySize, SMEM_GEMM_BYTES);
    cudaFuncSetAttribute(gemm_hf<1>, cudaFuncAttributeMaxDynamicSharedMemorySize, SMEM_GEMM_BYTES);
    cudaFuncSetAttribute(flash_attn, cudaFuncAttributeMaxDynamicSharedMemorySize, FA_SMEM);

    // 0) one-time conversions
    round_f32h<<<16384, 256>>>(x, xh);
    transpose_h<<<dim3(6144 / 32, 2048 / 32), dim3(32, 8)>>>(w_qkv, wqh, 2048, 6144);
    transpose_h<<<dim3(2048 / 32, 2048 / 32), dim3(32, 8)>>>(w_out, woh, 2048, 2048);

    // 1) QKV projection + fused RoPE; q,k,v stored fp16 directly
    gemm_hf<1><<<dim3(48, 64, 1), 256, SMEM_GEMM_BYTES>>>(
        xh, wqh, nullptr, 2048, 2048, 2048, 0, cosT, sinT);

    // 2) fused flash attention (2 CTAs/SM) -> g_ah fp16 [B,S,D]
    flash_attn<<<dim3(16, Bb_ * H_), 256, FA_SMEM>>>();

    // 3) out = attn @ w_outT^T
    gemm_hf<0><<<dim3(16, 64, 1), 256, SMEM_GEMM_BYTES>>>(
        ah, woh, out, 2048, 2048, 2048, 2048, nullptr, nullptr);
}